// round 15
// baseline (speedup 1.0000x reference)
#include <cuda_runtime.h>
#include <cuda_fp16.h>
#include <cstdint>
#include <cstddef>

#define B_  4
#define S_  2048
#define D_  512
#define H_  8
#define DEPTH 64
#define BH  (B_*H_)

#define QSCALE 0.1803368801111832f   // log2(e)/8
#define RS_SPLIT 4
#define PV_SPLIT 4

// ---------------- scratch ----------------
__device__ __half g_WT[(size_t)4*512*512];      // W^T fp16 [which][n][k]
__device__ __half g_Qh[(size_t)BH*S_*DEPTH];    // Q'·log2e/8 fp16 head-split
__device__ __half g_Kh[(size_t)BH*S_*DEPTH];    // K'' fp16 head-split
__device__ __half g_Vh[(size_t)BH*S_*DEPTH];    // V'  fp16 head-split
__device__ __half g_Vt[(size_t)BH*DEPTH*S_];    // V'^T fp16 (bh,d,t)
__device__ float  g_ctxp[(size_t)PV_SPLIT*B_*S_*D_];   // ctx partials
__device__ float  g_rsp[(size_t)RS_SPLIT*BH*S_];       // rowsum partials

// ---------------- helpers ----------------
__device__ __forceinline__ uint32_t pack2(float a, float b){
    __half2 h = __floats2half2_rn(a, b);
    return *(uint32_t*)&h;
}
__device__ __forceinline__ float ex2f(float x){
    float y; asm("ex2.approx.ftz.f32 %0, %1;" : "=f"(y) : "f"(x)); return y;
}
__device__ __forceinline__ uint32_t s2u(const void* p){
    uint32_t r; asm("{ .reg .u64 t; cvta.to.shared.u64 t, %1; cvt.u32.u64 %0, t; }"
                    : "=r"(r) : "l"(p)); return r;
}
__device__ __forceinline__ void mma16(float c[4], uint32_t a0,uint32_t a1,uint32_t a2,uint32_t a3,
                                      uint32_t b0,uint32_t b1){
    asm volatile("mma.sync.aligned.m16n8k16.row.col.f32.f16.f16.f32 "
        "{%0,%1,%2,%3}, {%4,%5,%6,%7}, {%8,%9}, {%0,%1,%2,%3};"
        : "+f"(c[0]),"+f"(c[1]),"+f"(c[2]),"+f"(c[3])
        : "r"(a0),"r"(a1),"r"(a2),"r"(a3),"r"(b0),"r"(b1));
}
__device__ __forceinline__ void ldsm4(uint32_t &r0,uint32_t &r1,uint32_t &r2,uint32_t &r3,
                                      uint32_t addr){
    asm volatile("ldmatrix.sync.aligned.m8n8.x4.shared.b16 {%0,%1,%2,%3}, [%4];"
        : "=r"(r0),"=r"(r1),"=r"(r2),"=r"(r3) : "r"(addr));
}

#define A_LANE_OFF(l, SW) (((((l)&7) + (((l)>>3)&1)*8) * (SW) + (((l)>>4)&1)*4) * 4)
#define B_LANE_OFF(l, SW) (((((l)&7) + (((l)>>4)&1)*8) * (SW) + (((l)>>3)&1)*4) * 4)

// ---------------- W transpose + fp16 convert ----------------
__global__ __launch_bounds__(256)
void transW(const float* Wq, const float* Wk, const float* Wv, const float* Wd)
{
    __shared__ float ts[64][65];
    const float* W = (blockIdx.z==0)?Wq:(blockIdx.z==1)?Wk:(blockIdx.z==2)?Wv:Wd;
    __half* WT = g_WT + (size_t)blockIdx.z*512*512;
    int k0 = blockIdx.y*64, n0 = blockIdx.x*64;
    int tid = threadIdx.x;
    #pragma unroll
    for (int i=0;i<4;i++){
        int e = tid + i*256;
        int r = e>>4, c = (e&15)*4;
        float4 x = *(const float4*)(W + (size_t)(k0+r)*512 + n0 + c);
        ts[r][c]=x.x; ts[r][c+1]=x.y; ts[r][c+2]=x.z; ts[r][c+3]=x.w;
    }
    __syncthreads();
    #pragma unroll
    for (int i=0;i<2;i++){
        int u = tid + i*256;
        int n = u>>3, seg = (u&7)*8;
        uint32_t h[4];
        #pragma unroll
        for (int j=0;j<4;j++)
            h[j] = pack2(ts[seg+2*j][n], ts[seg+2*j+1][n]);
        *(uint4*)(WT + (size_t)(n0+n)*512 + k0 + seg) = make_uint4(h[0],h[1],h[2],h[3]);
    }
}

// ---------------- V transpose ----------------
__global__ __launch_bounds__(256)
void transV()
{
    __shared__ __half ts[64][72];
    int tid = threadIdx.x;
    int bh = blockIdx.y, t0 = blockIdx.x*64;
    const __half* src = g_Vh + ((size_t)bh*S_ + t0)*DEPTH;
    #pragma unroll
    for (int i=0;i<2;i++){
        int u = tid + i*256;
        int r = u>>3, c = (u&7)*8;
        *(uint4*)&ts[r][c] = *(const uint4*)(src + (size_t)r*DEPTH + c);
    }
    __syncthreads();
    #pragma unroll
    for (int i=0;i<2;i++){
        int u = tid + i*256;
        int d = u>>3, seg = (u&7)*8;
        __half h[8];
        #pragma unroll
        for (int j=0;j<8;j++) h[j] = ts[seg+j][d];
        *(uint4*)(g_Vt + ((size_t)bh*DEPTH + d)*S_ + t0 + seg) = *(uint4*)h;
    }
}

// ---------------- fp16 GEMM core, 128x128 tiles (double-buffered smem) ----------------
// ADDA: sum PV_SPLIT ctx partial buffers (fixed order, deterministic).
template<int HALF_OUT, int ADDA>
__device__ __forceinline__ void gemm16_core(
    const float* __restrict__ A1,
    const __half* __restrict__ BT1, const float* __restrict__ bias1,
    const float* __restrict__ A2, const __half* __restrict__ BT2, const float* __restrict__ bias2,
    float* __restrict__ Cf, __half* __restrict__ Ch, int m0, int n0, float oscale,
    uint32_t (*As)[20], uint32_t (*Bs)[20])
{
    int tid = threadIdx.x;
    int lane = tid & 31, wid = tid >> 5;
    int g = lane >> 2, tg = lane & 3;
    int wm = wid & 3, wn = wid >> 2;

    float acc[2][8][4];
    #pragma unroll
    for (int i=0;i<2;i++)
        #pragma unroll
        for (int j=0;j<8;j++)
            #pragma unroll
            for (int r=0;r<4;r++) acc[i][j][r]=0.f;

    uint32_t aAddr = s2u(&As[0][0]) + (uint32_t)(wm*32*20*4) + A_LANE_OFF(lane, 20);
    uint32_t bAddr = s2u(&Bs[0][0]) + (uint32_t)(wn*64*20*4) + B_LANE_OFF(lane, 20);
    const uint32_t ABUF = 128*20*4, BBUF = 128*20*4;

    const int ntile = A2 ? 32 : 16;
    float4 ra[4]; uint4 rb2[2];
    auto ldg_tile = [&](int t){
        const float* A   = (t >= 16) ? A2  : A1;
        const __half* BT = (t >= 16) ? BT2 : BT1;
        int k0 = (t & 15) * 32;
        #pragma unroll
        for (int i=0;i<4;i++){
            int e = tid + i*256; int r = e>>3, c = (e&7)*4;
            ra[i] = *(const float4*)(A + (size_t)(m0+r)*512 + k0 + c);
            if (ADDA){
                #pragma unroll
                for (int zz=1; zz<PV_SPLIT; zz++){
                    float4 x = *(const float4*)(A + (size_t)zz*B_*S_*D_ + (size_t)(m0+r)*512 + k0 + c);
                    ra[i].x += x.x; ra[i].y += x.y; ra[i].z += x.z; ra[i].w += x.w;
                }
            }
        }
        int n = tid>>1, kc = (tid&1)*16;
        rb2[0] = *(const uint4*)(BT + (size_t)(n0+n)*512 + k0 + kc);
        rb2[1] = *(const uint4*)(BT + (size_t)(n0+n)*512 + k0 + kc + 8);
    };
    auto stage = [&](int buf){
        #pragma unroll
        for (int i=0;i<4;i++){
            int e = tid + i*256; int r = e>>3, c = (e&7)*4;
            *(uint2*)&As[buf*128 + r][c>>1] =
                make_uint2(pack2(ra[i].x, ra[i].y), pack2(ra[i].z, ra[i].w));
        }
        int n = tid>>1, seg = (tid&1)*8;
        *(uint4*)&Bs[buf*128 + n][seg]     = rb2[0];
        *(uint4*)&Bs[buf*128 + n][seg + 4] = rb2[1];
    };

    ldg_tile(0);
    stage(0);
    if (ntile > 1) ldg_tile(1);
    __syncthreads();

    for (int t = 0; t < ntile; t++){
        int b = t & 1;
        if (t+1 < ntile){
            stage(1-b);
            if (t+2 < ntile) ldg_tile(t+2);
        }
        uint32_t aA = aAddr + (uint32_t)b*ABUF;
        uint32_t bA = bAddr + (uint32_t)b*BBUF;
        #pragma unroll
        for (int s=0; s<2; s++){
            uint32_t koff = (uint32_t)(s*32);
            uint32_t a0[4], a1[4], bb[4][4];
            ldsm4(a0[0],a0[1],a0[2],a0[3], aA + koff);
            ldsm4(a1[0],a1[1],a1[2],a1[3], aA + (uint32_t)(16*20*4) + koff);
            #pragma unroll
            for (int rb=0; rb<4; rb++)
                ldsm4(bb[rb][0],bb[rb][1],bb[rb][2],bb[rb][3],
                      bA + (uint32_t)(rb*16*20*4) + koff);
            #pragma unroll
            for (int rb=0; rb<4; rb++){
                mma16(acc[0][2*rb  ], a0[0],a0[1],a0[2],a0[3], bb[rb][0],bb[rb][1]);
                mma16(acc[0][2*rb+1], a0[0],a0[1],a0[2],a0[3], bb[rb][2],bb[rb][3]);
                mma16(acc[1][2*rb  ], a1[0],a1[1],a1[2],a1[3], bb[rb][0],bb[rb][1]);
                mma16(acc[1][2*rb+1], a1[0],a1[1],a1[2],a1[3], bb[rb][2],bb[rb][3]);
            }
        }
        __syncthreads();
    }

    #pragma unroll
    for (int mi=0;mi<2;mi++)
        #pragma unroll
        for (int ni=0;ni<8;ni++)
            #pragma unroll
            for (int half=0; half<2; half++){
                int row = m0 + wm*32 + mi*16 + g + half*8;
                int col = n0 + wn*64 + ni*8 + tg*2;
                float b0v = bias1[col]   + (bias2 ? bias2[col]   : 0.f);
                float b1v = bias1[col+1] + (bias2 ? bias2[col+1] : 0.f);
                float v0 = (acc[mi][ni][half*2+0] + b0v) * oscale;
                float v1 = (acc[mi][ni][half*2+1] + b1v) * oscale;
                if (HALF_OUT){
                    int b = row >> 11, s = row & 2047;
                    int h = col >> 6,  d = col & 63;
                    size_t idx = (((size_t)(b*H_ + h))*S_ + s)*DEPTH + d;
                    *(uint32_t*)(Ch + idx) = pack2(v0, v1);
                } else {
                    *(float2*)(Cf + (size_t)row*512 + col) = make_float2(v0, v1);
                }
            }
}

__global__ __launch_bounds__(256, 2)
void proj3(const float* q, const float* k, const float* pe, const float* v,
           const float* bq, const float* bk, const float* bv, const float* bd)
{
    __shared__ uint32_t As[2*128][20];
    __shared__ uint32_t Bs[2*128][20];
    int m0 = blockIdx.y*128, n0 = blockIdx.x*128;
    const __half* WqT = g_WT;
    const __half* WkT = g_WT + (size_t)512*512;
    const __half* WvT = g_WT + (size_t)2*512*512;
    const __half* WdT = g_WT + (size_t)3*512*512;
    if (blockIdx.z == 0)
        gemm16_core<1,0>(q, WqT, bq, nullptr,nullptr,nullptr, nullptr, g_Qh, m0,n0, QSCALE, As,Bs);
    else if (blockIdx.z == 1)
        gemm16_core<1,0>(k, WkT, bk, pe, WdT, bd, nullptr, g_Kh, m0,n0, 1.f, As,Bs);
    else
        gemm16_core<1,0>(v, WvT, bv, nullptr,nullptr,nullptr, nullptr, g_Vh, m0,n0, 1.f, As,Bs);
}

__global__ __launch_bounds__(256, 2)
void gemm_out(const float* __restrict__ A,
              const float* __restrict__ bd, float* __restrict__ C)
{
    __shared__ uint32_t As[2*128][20];
    __shared__ uint32_t Bs[2*128][20];
    gemm16_core<0,1>(A, g_WT + (size_t)3*512*512, bd, nullptr,nullptr,nullptr, C, nullptr,
                     blockIdx.y*128, blockIdx.x*128, 1.f, As, Bs);
}

// ---------------- pass 1: partial rowsums of exp(logits), split over t ----------------
__global__ __launch_bounds__(256, 4)
void attn_rowsum()
{
    extern __shared__ uint32_t sm1[];
    uint32_t (*Qs)[36] = (uint32_t(*)[36])sm1;                    // 128
    uint32_t (*Ks)[36] = (uint32_t(*)[36])(sm1 + 128*36);         // 2 x 64
    float *rs = (float*)(sm1 + 128*36 + 2*64*36);

    const int TS = 32 / RS_SPLIT;    // tiles per split
    int tid = threadIdx.x;
    int lane = tid & 31, wid = tid >> 5;
    int g = lane >> 2, tg = lane & 3;
    int wm = wid & 3, wn = wid >> 2;
    int bh = blockIdx.y;
    int s0 = blockIdx.x * 128;
    int z  = blockIdx.z;

    const __half* qh = g_Qh + ((size_t)bh*S_ + s0)*DEPTH;
    const __half* kh = g_Kh + ((size_t)bh*S_ + z*(S_/RS_SPLIT))*DEPTH;

    uint32_t qAddr = s2u(&Qs[0][0]) + (uint32_t)(wm*32*36*4) + A_LANE_OFF(lane, 36);
    uint32_t kAddr = s2u(&Ks[0][0]) + (uint32_t)(wn*32*36*4) + B_LANE_OFF(lane, 36);
    const uint32_t KBUF = 64*36*4;

    #pragma unroll
    for (int i=0;i<4;i++){
        int u = tid + i*256;
        int r = u>>3, c8 = u&7;
        *(uint4*)&Qs[r][c8*4] = *(const uint4*)(qh + (size_t)r*DEPTH + c8*8);
    }
    if (tid < 128) rs[tid] = 0.f;

    uint4 kr[2];
    auto ldgK = [&](int t0){
        #pragma unroll
        for (int i=0;i<2;i++){
            int u = tid + i*256;
            int r = u>>3, c8 = u&7;
            kr[i] = *(const uint4*)(kh + (size_t)(t0+r)*DEPTH + c8*8);
        }
    };
    auto stageK = [&](int buf){
        #pragma unroll
        for (int i=0;i<2;i++){
            int u = tid + i*256;
            int r = u>>3, c8 = u&7;
            *(uint4*)&Ks[buf*64 + r][c8*4] = kr[i];
        }
    };

    ldgK(0);
    stageK(0);
    if (TS > 1) ldgK(64);
    __syncthreads();

    float rowacc[4] = {0.f,0.f,0.f,0.f};

    for (int ti = 0; ti < TS; ti++){
        int b = ti & 1;
        if (ti + 1 < TS){
            stageK(1-b);
            if (ti + 2 < TS) ldgK((ti+2)*64);
        }
        uint32_t kA = kAddr + (uint32_t)b*KBUF;

        float acc[2][4][4];
        #pragma unroll
        for (int i=0;i<2;i++)
            #pragma unroll
            for (int j=0;j<4;j++)
                #pragma unroll
                for (int r=0;r<4;r++) acc[i][j][r]=0.f;

        #pragma unroll
        for (int s=0; s<4; s++){
            uint32_t koff = (uint32_t)(s*32);
            uint32_t a0[4], a1[4], b0[4], b1[4];
            ldsm4(a0[0],a0[1],a0[2],a0[3], qAddr + koff);
            ldsm4(a1[0],a1[1],a1[2],a1[3], qAddr + (uint32_t)(16*36*4) + koff);
            ldsm4(b0[0],b0[1],b0[2],b0[3], kA + koff);
            ldsm4(b1[0],b1[1],b1[2],b1[3], kA + (uint32_t)(16*36*4) + koff);
            mma16(acc[0][0], a0[0],a0[1],a0[2],a0[3], b0[0],b0[1]);
            mma16(acc[0][1], a0[0],a0[1],a0[2],a0[3], b0[2],b0[3]);
            mma16(acc[0][2], a0[0],a0[1],a0[2],a0[3], b1[0],b1[1]);
            mma16(acc[0][3], a0[0],a0[1],a0[2],a0[3], b1[2],b1[3]);
            mma16(acc[1][0], a1[0],a1[1],a1[2],a1[3], b0[0],b0[1]);
            mma16(acc[1][1], a1[0],a1[1],a1[2],a1[3], b0[2],b0[3]);
            mma16(acc[1][2], a1[0],a1[1],a1[2],a1[3], b1[0],b1[1]);
            mma16(acc[1][3], a1[0],a1[1],a1[2],a1[3], b1[2],b1[3]);
        }
        #pragma unroll
        for (int mi=0;mi<2;mi++)
            #pragma unroll
            for (int ni=0;ni<4;ni++)
                #pragma unroll
                for (int r2=0;r2<4;r2++)
                    rowacc[mi*2 + (r2>>1)] += ex2f(acc[mi][ni][r2]);
        __syncthreads();
    }

    #pragma unroll
    for (int i=0;i<4;i++){
        float v = rowacc[i];
        v += __shfl_xor_sync(0xffffffffu, v, 1);
        v += __shfl_xor_sync(0xffffffffu, v, 2);
        if (tg == 0){
            int row = wm*32 + (i>>1)*16 + g + (i&1)*8;
            atomicAdd(&rs[row], v);
        }
    }
    __syncthreads();
    if (tid < 128)
        g_rsp[(size_t)z*BH*S_ + (size_t)bh*S_ + s0 + tid] = rs[tid];
}

// ---------------- pass 2: attn write + partial ctx = attn @ V, split over t ----------------
__global__ __launch_bounds__(256)
void attn_pv(float* __restrict__ attn)
{
    extern __shared__ uint32_t sm2[];
    uint32_t (*Qs)[36] = (uint32_t(*)[36])sm2;                          // 128
    uint32_t (*Ks)[36] = (uint32_t(*)[36])(sm2 + 128*36);               // 2 x 64
    uint32_t (*Vs)[36] = (uint32_t(*)[36])(sm2 + 256*36);               // 2 x 64
    float *rsv = (float*)(sm2 + 384*36);                                // 128
    float (*sctx)[66] = (float(*)[66])sm2;                              // alias (epilogue)

    const int TS = 32 / PV_SPLIT;
    int tid = threadIdx.x;
    int lane = tid & 31, wid = tid >> 5;
    int g = lane >> 2, tg = lane & 3;
    int wm = wid & 3, wn = wid >> 2;
    int bh = blockIdx.y;
    int s0 = blockIdx.x * 128;
    int z  = blockIdx.z;
    int tbase = z * (S_/PV_SPLIT);

    const __half* qh = g_Qh + ((size_t)bh*S_ + s0)*DEPTH;
    const __half* kh = g_Kh + ((size_t)bh*S_ + tbase)*DEPTH;
    const __half* vt = g_Vt +  (size_t)bh*DEPTH*S_ + tbase;
    float* attn_strip = attn + ((size_t)bh*S_ + s0)*S_ + tbase;
    float* ctxp = g_ctxp + (size_t)z*B_*S_*D_;

    uint32_t qAddr = s2u(&Qs[0][0]) + (uint32_t)(wm*32*36*4) + A_LANE_OFF(lane, 36);
    uint32_t kAddr = s2u(&Ks[0][0]) + (uint32_t)(wn*32*36*4) + B_LANE_OFF(lane, 36);
    uint32_t vAddr = s2u(&Vs[0][0]) + B_LANE_OFF(lane, 36);
    const uint32_t TBUF = 64*36*4;

    #pragma unroll
    for (int i=0;i<4;i++){
        int u = tid + i*256;
        int r = u>>3, c8 = u&7;
        *(uint4*)&Qs[r][c8*4] = *(const uint4*)(qh + (size_t)r*DEPTH + c8*8);
    }
    if (tid < 128){
        size_t idx = (size_t)bh*S_ + s0 + tid;
        float s = 0.f;
        #pragma unroll
        for (int zz=0; zz<RS_SPLIT; zz++) s += g_rsp[(size_t)zz*BH*S_ + idx];
        rsv[tid] = 1.0f / s;
    }

    uint4 kr[2], vr[2];
    auto ldgKV = [&](int t0){
        #pragma unroll
        for (int i=0;i<2;i++){
            int u = tid + i*256;
            int r = u>>3, c8 = u&7;
            kr[i] = *(const uint4*)(kh + (size_t)(t0+r)*DEPTH + c8*8);
            vr[i] = *(const uint4*)(vt + (size_t)r*S_ + t0 + c8*8);
        }
    };
    auto stageKV = [&](int buf){
        #pragma unroll
        for (int i=0;i<2;i++){
            int u = tid + i*256;
            int r = u>>3, c8 = u&7;
            *(uint4*)&Ks[buf*64 + r][c8*4] = kr[i];
            *(uint4*)&Vs[buf*64 + r][c8*4] = vr[i];
        }
    };

    ldgKV(0);
    stageKV(0);
    if (TS > 1) ldgKV(64);
    __syncthreads();

    float octx[2][8][4];
    #pragma unroll
    for (int i=0;i<2;i++)
        #pragma unroll
        for (int j=0;j<8;j++)
            #pragma unroll
            for (int r=0;r<4;r++) octx[i][j][r]=0.f;

    for (int ti = 0; ti < TS; ti++){
        int b = ti & 1;
        int t0 = ti*64;
        if (ti + 1 < TS){
            stageKV(1-b);
            if (ti + 2 < TS) ldgKV((ti+2)*64);
        }
        uint32_t kA = kAddr + (uint32_t)b*TBUF;
        uint32_t vA = vAddr + (uint32_t)b*TBUF;

        float acc[2][4][4];
        #pragma unroll
        for (int i=0;i<2;i++)
            #pragma unroll
            for (int j=0;j<4;j++)
                #pragma unroll
                for (int r=0;r<4;r++) acc[i][j][r]=0.f;

        #pragma unroll
        for (int s=0; s<4; s++){
            uint32_t koff = (uint32_t)(s*32);
            uint32_t a0[4], a1[4], b0[4], b1[4];
            ldsm4(a0[0],a0[1],a0[2],a0[3], qAddr + koff);
            ldsm4(a1[0],a1[1],a1[2],a1[3], qAddr + (uint32_t)(16*36*4) + koff);
            ldsm4(b0[0],b0[1],b0[2],b0[3], kA + koff);
            ldsm4(b1[0],b1[1],b1[2],b1[3], kA + (uint32_t)(16*36*4) + koff);
            mma16(acc[0][0], a0[0],a0[1],a0[2],a0[3], b0[0],b0[1]);
            mma16(acc[0][1], a0[0],a0[1],a0[2],a0[3], b0[2],b0[3]);
            mma16(acc[0][2], a0[0],a0[1],a0[2],a0[3], b1[0],b1[1]);
            mma16(acc[0][3], a0[0],a0[1],a0[2],a0[3], b1[2],b1[3]);
            mma16(acc[1][0], a1[0],a1[1],a1[2],a1[3], b0[0],b0[1]);
            mma16(acc[1][1], a1[0],a1[1],a1[2],a1[3], b0[2],b0[3]);
            mma16(acc[1][2], a1[0],a1[1],a1[2],a1[3], b1[0],b1[1]);
            mma16(acc[1][3], a1[0],a1[1],a1[2],a1[3], b1[2],b1[3]);
        }

        #pragma unroll
        for (int mi=0;mi<2;mi++){
            int r0 = wm*32 + mi*16 + g;
            float inv0 = rsv[r0], inv1 = rsv[r0+8];
            #pragma unroll
            for (int ni=0;ni<4;ni++){
                acc[mi][ni][0] = ex2f(acc[mi][ni][0])*inv0;
                acc[mi][ni][1] = ex2f(acc[mi][ni][1])*inv0;
                acc[mi][ni][2] = ex2f(acc[mi][ni][2])*inv1;
                acc[mi][ni][3] = ex2f(acc[mi][ni][3])*inv1;
            }
        }
        #pragma unroll
        for (int mi=0;mi<2;mi++)
            #pragma unroll
            for (int ni=0;ni<4;ni++)
                #pragma unroll
                for (int half=0; half<2; half++){
                    int rloc = wm*32 + mi*16 + g + half*8;
                    int cloc = wn*32 + ni*8 + tg*2;
                    *(float2*)(attn_strip + (size_t)rloc*S_ + t0 + cloc) =
                        make_float2(acc[mi][ni][half*2], acc[mi][ni][half*2+1]);
                }

        #pragma unroll
        for (int j=0; j<2; j++){
            uint32_t pa[2][4];
            #pragma unroll
            for (int mi=0;mi<2;mi++){
                pa[mi][0] = pack2(acc[mi][2*j  ][0], acc[mi][2*j  ][1]);
                pa[mi][1] = pack2(acc[mi][2*j  ][2], acc[mi][2*j  ][3]);
                pa[mi][2] = pack2(acc[mi][2*j+1][0], acc[mi][2*j+1][1]);
                pa[mi][3] = pack2(acc[mi][2*j+1][2], acc[mi][2*j+1][3]);
            }
            uint32_t koff = (uint32_t)((wn*16 + j*8)*4);
            #pragma unroll
            for (int rb=0; rb<4; rb++){
                uint32_t b2[4];
                ldsm4(b2[0],b2[1],b2[2],b2[3], vA + (uint32_t)(rb*16*36*4) + koff);
                mma16(octx[0][2*rb  ], pa[0][0],pa[0][1],pa[0][2],pa[0][3], b2[0],b2[1]);
                mma16(octx[0][2*rb+1], pa[0][0],pa[0][1],pa[0][2],pa[0][3], b2[2],b2[3]);
                mma16(octx[1][2*rb  ], pa[1][0],pa[1][1],pa[1][2],pa[1][3], b2[0],b2[1]);
                mma16(octx[1][2*rb+1], pa[1][0],pa[1][1],pa[1][2],pa[1][3], b2[2],b2[3]);
            }
        }
        __syncthreads();
    }

    // cross-warp (wn) reduction of partial ctx, then write partial buffer
    if (wn == 1){
        #pragma unroll
        for (int mi=0;mi<2;mi++)
            #pragma unroll
            for (int ni=0;ni<8;ni++)
                #pragma unroll
                for (int half=0; half<2; half++){
                    int rloc = wm*32 + mi*16 + g + half*8;
                    int col = ni*8 + tg*2;
                    sctx[rloc][col]   = octx[mi][ni][half*2];
                    sctx[rloc][col+1] = octx[mi][ni][half*2+1];
                }
    }
    __syncthreads();
    if (wn == 0){
        int b = bh >> 3, h = bh & 7;
        #pragma unroll
        for (int mi=0;mi<2;mi++)
            #pragma unroll
            for (int ni=0;ni<8;ni++)
                #pragma unroll
                for (int half=0; half<2; half++){
                    int rloc = wm*32 + mi*16 + g + half*8;
                    int col = ni*8 + tg*2;
                    float v0 = octx[mi][ni][half*2]   + sctx[rloc][col];
                    float v1 = octx[mi][ni][half*2+1] + sctx[rloc][col+1];
                    *(float2*)(ctxp + ((size_t)b*S_ + s0 + rloc)*D_ + h*64 + col) =
                        make_float2(v0, v1);
                }
    }
}

// ---------------- launch ----------------
extern "C" void kernel_launch(void* const* d_in, const int* in_sizes, int n_in,
                              void* d_out, int out_size)
{
    const float* q   = (const float*)d_in[0];
    const float* k   = (const float*)d_in[1];
    const float* v   = (const float*)d_in[2];
    const float* pe  = (const float*)d_in[3];
    // d_in[4] = mask (unused by reference)
    const float* Wq  = (const float*)d_in[5];
    const float* bq  = (const float*)d_in[6];
    const float* Wk  = (const float*)d_in[7];
    const float* bk  = (const float*)d_in[8];
    const float* Wv  = (const float*)d_in[9];
    const float* bv  = (const float*)d_in[10];
    const float* Wd  = (const float*)d_in[11];
    const float* bd  = (const float*)d_in[12];

    float* out  = (float*)d_out;                       // (B,S,D)
    float* attn = out + (size_t)B_*S_*D_;              // (B,H,S,S)

    float* Ctxp;
    cudaGetSymbolAddress((void**)&Ctxp, g_ctxp);

    transW<<<dim3(8, 8, 4), 256>>>(Wq, Wk, Wv, Wd);
    proj3<<<dim3(4, 64, 3), 256>>>(q, k, pe, v, bq, bk, bv, bd);
    transV<<<dim3(S_/64, BH), 256>>>();

    size_t smA = (size_t)(128*36 + 2*64*36)*sizeof(uint32_t) + 128*sizeof(float);
    cudaFuncSetAttribute(attn_rowsum, cudaFuncAttributeMaxDynamicSharedMemorySize, (int)smA);
    attn_rowsum<<<dim3(16, BH, RS_SPLIT), 256, smA>>>();

    size_t smB = (size_t)(128*36 + 4*64*36)*sizeof(uint32_t) + 128*sizeof(float);
    cudaFuncSetAttribute(attn_pv, cudaFuncAttributeMaxDynamicSharedMemorySize, (int)smB);
    attn_pv<<<dim3(16, BH, PV_SPLIT), 256, smB>>>(attn);

    gemm_out<<<dim3(4, 64), 256>>>(Ctxp, bd, out);
}

// round 16
// speedup vs baseline: 1.1037x; 1.1037x over previous
#include <cuda_runtime.h>
#include <cuda_fp16.h>
#include <cstdint>
#include <cstddef>

#define B_  4
#define S_  2048
#define D_  512
#define H_  8
#define DEPTH 64
#define BH  (B_*H_)

#define QSCALE 0.1803368801111832f   // log2(e)/8
#define RS_SPLIT 4
#define PV_SPLIT 2

// ---------------- scratch ----------------
__device__ __half g_WT[(size_t)4*512*512];      // W^T fp16 [which][n][k]
__device__ __half g_Qh[(size_t)BH*S_*DEPTH];    // Q'·log2e/8 fp16 head-split
__device__ __half g_Kh[(size_t)BH*S_*DEPTH];    // K'' fp16 head-split
__device__ __half g_Vh[(size_t)BH*S_*DEPTH];    // V'  fp16 head-split
__device__ __half g_Vt[(size_t)BH*DEPTH*S_];    // V'^T fp16 (bh,d,t)
__device__ float  g_ctxp[(size_t)PV_SPLIT*B_*S_*D_];   // ctx partials
__device__ float  g_rsp[(size_t)RS_SPLIT*BH*S_];       // rowsum partials

// ---------------- helpers ----------------
__device__ __forceinline__ uint32_t pack2(float a, float b){
    __half2 h = __floats2half2_rn(a, b);
    return *(uint32_t*)&h;
}
__device__ __forceinline__ float ex2f(float x){
    float y; asm("ex2.approx.ftz.f32 %0, %1;" : "=f"(y) : "f"(x)); return y;
}
__device__ __forceinline__ uint32_t s2u(const void* p){
    uint32_t r; asm("{ .reg .u64 t; cvta.to.shared.u64 t, %1; cvt.u32.u64 %0, t; }"
                    : "=r"(r) : "l"(p)); return r;
}
__device__ __forceinline__ void mma16(float c[4], uint32_t a0,uint32_t a1,uint32_t a2,uint32_t a3,
                                      uint32_t b0,uint32_t b1){
    asm volatile("mma.sync.aligned.m16n8k16.row.col.f32.f16.f16.f32 "
        "{%0,%1,%2,%3}, {%4,%5,%6,%7}, {%8,%9}, {%0,%1,%2,%3};"
        : "+f"(c[0]),"+f"(c[1]),"+f"(c[2]),"+f"(c[3])
        : "r"(a0),"r"(a1),"r"(a2),"r"(a3),"r"(b0),"r"(b1));
}
__device__ __forceinline__ void ldsm4(uint32_t &r0,uint32_t &r1,uint32_t &r2,uint32_t &r3,
                                      uint32_t addr){
    asm volatile("ldmatrix.sync.aligned.m8n8.x4.shared.b16 {%0,%1,%2,%3}, [%4];"
        : "=r"(r0),"=r"(r1),"=r"(r2),"=r"(r3) : "r"(addr));
}

#define A_LANE_OFF(l, SW) (((((l)&7) + (((l)>>3)&1)*8) * (SW) + (((l)>>4)&1)*4) * 4)
#define B_LANE_OFF(l, SW) (((((l)&7) + (((l)>>4)&1)*8) * (SW) + (((l)>>3)&1)*4) * 4)

// ---------------- W transpose + fp16 convert ----------------
__global__ __launch_bounds__(256)
void transW(const float* Wq, const float* Wk, const float* Wv, const float* Wd)
{
    __shared__ float ts[64][65];
    const float* W = (blockIdx.z==0)?Wq:(blockIdx.z==1)?Wk:(blockIdx.z==2)?Wv:Wd;
    __half* WT = g_WT + (size_t)blockIdx.z*512*512;
    int k0 = blockIdx.y*64, n0 = blockIdx.x*64;
    int tid = threadIdx.x;
    #pragma unroll
    for (int i=0;i<4;i++){
        int e = tid + i*256;
        int r = e>>4, c = (e&15)*4;
        float4 x = *(const float4*)(W + (size_t)(k0+r)*512 + n0 + c);
        ts[r][c]=x.x; ts[r][c+1]=x.y; ts[r][c+2]=x.z; ts[r][c+3]=x.w;
    }
    __syncthreads();
    #pragma unroll
    for (int i=0;i<2;i++){
        int u = tid + i*256;
        int n = u>>3, seg = (u&7)*8;
        uint32_t h[4];
        #pragma unroll
        for (int j=0;j<4;j++)
            h[j] = pack2(ts[seg+2*j][n], ts[seg+2*j+1][n]);
        *(uint4*)(WT + (size_t)(n0+n)*512 + k0 + seg) = make_uint4(h[0],h[1],h[2],h[3]);
    }
}

// ---------------- V transpose ----------------
__global__ __launch_bounds__(256)
void transV()
{
    __shared__ __half ts[64][72];
    int tid = threadIdx.x;
    int bh = blockIdx.y, t0 = blockIdx.x*64;
    const __half* src = g_Vh + ((size_t)bh*S_ + t0)*DEPTH;
    #pragma unroll
    for (int i=0;i<2;i++){
        int u = tid + i*256;
        int r = u>>3, c = (u&7)*8;
        *(uint4*)&ts[r][c] = *(const uint4*)(src + (size_t)r*DEPTH + c);
    }
    __syncthreads();
    #pragma unroll
    for (int i=0;i<2;i++){
        int u = tid + i*256;
        int d = u>>3, seg = (u&7)*8;
        __half h[8];
        #pragma unroll
        for (int j=0;j<8;j++) h[j] = ts[seg+j][d];
        *(uint4*)(g_Vt + ((size_t)bh*DEPTH + d)*S_ + t0 + seg) = *(uint4*)h;
    }
}

// ---------------- fp16 GEMM core, 128x128 tiles (double-buffered smem) ----------------
// ADDA: sum PV_SPLIT ctx partial buffers (fixed order, deterministic).
template<int HALF_OUT, int ADDA>
__device__ __forceinline__ void gemm16_core(
    const float* __restrict__ A1,
    const __half* __restrict__ BT1, const float* __restrict__ bias1,
    const float* __restrict__ A2, const __half* __restrict__ BT2, const float* __restrict__ bias2,
    float* __restrict__ Cf, __half* __restrict__ Ch, int m0, int n0, float oscale,
    uint32_t (*As)[20], uint32_t (*Bs)[20])
{
    int tid = threadIdx.x;
    int lane = tid & 31, wid = tid >> 5;
    int g = lane >> 2, tg = lane & 3;
    int wm = wid & 3, wn = wid >> 2;

    float acc[2][8][4];
    #pragma unroll
    for (int i=0;i<2;i++)
        #pragma unroll
        for (int j=0;j<8;j++)
            #pragma unroll
            for (int r=0;r<4;r++) acc[i][j][r]=0.f;

    uint32_t aAddr = s2u(&As[0][0]) + (uint32_t)(wm*32*20*4) + A_LANE_OFF(lane, 20);
    uint32_t bAddr = s2u(&Bs[0][0]) + (uint32_t)(wn*64*20*4) + B_LANE_OFF(lane, 20);
    const uint32_t ABUF = 128*20*4, BBUF = 128*20*4;

    const int ntile = A2 ? 32 : 16;
    float4 ra[4]; uint4 rb2[2];
    auto ldg_tile = [&](int t){
        const float* A   = (t >= 16) ? A2  : A1;
        const __half* BT = (t >= 16) ? BT2 : BT1;
        int k0 = (t & 15) * 32;
        #pragma unroll
        for (int i=0;i<4;i++){
            int e = tid + i*256; int r = e>>3, c = (e&7)*4;
            ra[i] = *(const float4*)(A + (size_t)(m0+r)*512 + k0 + c);
            if (ADDA){
                #pragma unroll
                for (int zz=1; zz<PV_SPLIT; zz++){
                    float4 x = *(const float4*)(A + (size_t)zz*B_*S_*D_ + (size_t)(m0+r)*512 + k0 + c);
                    ra[i].x += x.x; ra[i].y += x.y; ra[i].z += x.z; ra[i].w += x.w;
                }
            }
        }
        int n = tid>>1, kc = (tid&1)*16;
        rb2[0] = *(const uint4*)(BT + (size_t)(n0+n)*512 + k0 + kc);
        rb2[1] = *(const uint4*)(BT + (size_t)(n0+n)*512 + k0 + kc + 8);
    };
    auto stage = [&](int buf){
        #pragma unroll
        for (int i=0;i<4;i++){
            int e = tid + i*256; int r = e>>3, c = (e&7)*4;
            *(uint2*)&As[buf*128 + r][c>>1] =
                make_uint2(pack2(ra[i].x, ra[i].y), pack2(ra[i].z, ra[i].w));
        }
        int n = tid>>1, seg = (tid&1)*8;
        *(uint4*)&Bs[buf*128 + n][seg]     = rb2[0];
        *(uint4*)&Bs[buf*128 + n][seg + 4] = rb2[1];
    };

    ldg_tile(0);
    stage(0);
    if (ntile > 1) ldg_tile(1);
    __syncthreads();

    for (int t = 0; t < ntile; t++){
        int b = t & 1;
        if (t+1 < ntile){
            stage(1-b);
            if (t+2 < ntile) ldg_tile(t+2);
        }
        uint32_t aA = aAddr + (uint32_t)b*ABUF;
        uint32_t bA = bAddr + (uint32_t)b*BBUF;
        #pragma unroll
        for (int s=0; s<2; s++){
            uint32_t koff = (uint32_t)(s*32);
            uint32_t a0[4], a1[4], bb[4][4];
            ldsm4(a0[0],a0[1],a0[2],a0[3], aA + koff);
            ldsm4(a1[0],a1[1],a1[2],a1[3], aA + (uint32_t)(16*20*4) + koff);
            #pragma unroll
            for (int rb=0; rb<4; rb++)
                ldsm4(bb[rb][0],bb[rb][1],bb[rb][2],bb[rb][3],
                      bA + (uint32_t)(rb*16*20*4) + koff);
            #pragma unroll
            for (int rb=0; rb<4; rb++){
                mma16(acc[0][2*rb  ], a0[0],a0[1],a0[2],a0[3], bb[rb][0],bb[rb][1]);
                mma16(acc[0][2*rb+1], a0[0],a0[1],a0[2],a0[3], bb[rb][2],bb[rb][3]);
                mma16(acc[1][2*rb  ], a1[0],a1[1],a1[2],a1[3], bb[rb][0],bb[rb][1]);
                mma16(acc[1][2*rb+1], a1[0],a1[1],a1[2],a1[3], bb[rb][2],bb[rb][3]);
            }
        }
        __syncthreads();
    }

    #pragma unroll
    for (int mi=0;mi<2;mi++)
        #pragma unroll
        for (int ni=0;ni<8;ni++)
            #pragma unroll
            for (int half=0; half<2; half++){
                int row = m0 + wm*32 + mi*16 + g + half*8;
                int col = n0 + wn*64 + ni*8 + tg*2;
                float b0v = bias1[col]   + (bias2 ? bias2[col]   : 0.f);
                float b1v = bias1[col+1] + (bias2 ? bias2[col+1] : 0.f);
                float v0 = (acc[mi][ni][half*2+0] + b0v) * oscale;
                float v1 = (acc[mi][ni][half*2+1] + b1v) * oscale;
                if (HALF_OUT){
                    int b = row >> 11, s = row & 2047;
                    int h = col >> 6,  d = col & 63;
                    size_t idx = (((size_t)(b*H_ + h))*S_ + s)*DEPTH + d;
                    *(uint32_t*)(Ch + idx) = pack2(v0, v1);
                } else {
                    *(float2*)(Cf + (size_t)row*512 + col) = make_float2(v0, v1);
                }
            }
}

__global__ __launch_bounds__(256, 2)
void proj3(const float* q, const float* k, const float* pe, const float* v,
           const float* bq, const float* bk, const float* bv, const float* bd)
{
    __shared__ uint32_t As[2*128][20];
    __shared__ uint32_t Bs[2*128][20];
    int m0 = blockIdx.y*128, n0 = blockIdx.x*128;
    const __half* WqT = g_WT;
    const __half* WkT = g_WT + (size_t)512*512;
    const __half* WvT = g_WT + (size_t)2*512*512;
    const __half* WdT = g_WT + (size_t)3*512*512;
    if (blockIdx.z == 0)
        gemm16_core<1,0>(q, WqT, bq, nullptr,nullptr,nullptr, nullptr, g_Qh, m0,n0, QSCALE, As,Bs);
    else if (blockIdx.z == 1)
        gemm16_core<1,0>(k, WkT, bk, pe, WdT, bd, nullptr, g_Kh, m0,n0, 1.f, As,Bs);
    else
        gemm16_core<1,0>(v, WvT, bv, nullptr,nullptr,nullptr, nullptr, g_Vh, m0,n0, 1.f, As,Bs);
}

__global__ __launch_bounds__(256, 2)
void gemm_out(const float* __restrict__ A,
              const float* __restrict__ bd, float* __restrict__ C)
{
    __shared__ uint32_t As[2*128][20];
    __shared__ uint32_t Bs[2*128][20];
    gemm16_core<0,1>(A, g_WT + (size_t)3*512*512, bd, nullptr,nullptr,nullptr, C, nullptr,
                     blockIdx.y*128, blockIdx.x*128, 1.f, As, Bs);
}

// ---------------- pass 1: partial rowsums of exp(logits), split over t ----------------
// Q fragments hoisted out of the t-loop (loop-invariant): halves per-tile LDSM traffic.
__global__ __launch_bounds__(256)
void attn_rowsum()
{
    extern __shared__ uint32_t sm1[];
    uint32_t (*Qs)[36] = (uint32_t(*)[36])sm1;                    // 128
    uint32_t (*Ks)[36] = (uint32_t(*)[36])(sm1 + 128*36);         // 2 x 64
    float *rs = (float*)(sm1 + 128*36 + 2*64*36);

    const int TS = 32 / RS_SPLIT;    // tiles per split
    int tid = threadIdx.x;
    int lane = tid & 31, wid = tid >> 5;
    int g = lane >> 2, tg = lane & 3;
    int wm = wid & 3, wn = wid >> 2;
    int bh = blockIdx.y;
    int s0 = blockIdx.x * 128;
    int z  = blockIdx.z;

    const __half* qh = g_Qh + ((size_t)bh*S_ + s0)*DEPTH;
    const __half* kh = g_Kh + ((size_t)bh*S_ + z*(S_/RS_SPLIT))*DEPTH;

    uint32_t qAddr = s2u(&Qs[0][0]) + (uint32_t)(wm*32*36*4) + A_LANE_OFF(lane, 36);
    uint32_t kAddr = s2u(&Ks[0][0]) + (uint32_t)(wn*32*36*4) + B_LANE_OFF(lane, 36);
    const uint32_t KBUF = 64*36*4;

    #pragma unroll
    for (int i=0;i<4;i++){
        int u = tid + i*256;
        int r = u>>3, c8 = u&7;
        *(uint4*)&Qs[r][c8*4] = *(const uint4*)(qh + (size_t)r*DEPTH + c8*8);
    }
    if (tid < 128) rs[tid] = 0.f;

    uint4 kr[2];
    auto ldgK = [&](int t0){
        #pragma unroll
        for (int i=0;i<2;i++){
            int u = tid + i*256;
            int r = u>>3, c8 = u&7;
            kr[i] = *(const uint4*)(kh + (size_t)(t0+r)*DEPTH + c8*8);
        }
    };
    auto stageK = [&](int buf){
        #pragma unroll
        for (int i=0;i<2;i++){
            int u = tid + i*256;
            int r = u>>3, c8 = u&7;
            *(uint4*)&Ks[buf*64 + r][c8*4] = kr[i];
        }
    };

    ldgK(0);
    stageK(0);
    if (TS > 1) ldgK(64);
    __syncthreads();

    // hoist Q fragments (loop-invariant)
    uint32_t qa[2][4][4];
    #pragma unroll
    for (int s=0; s<4; s++){
        uint32_t koff = (uint32_t)(s*32);
        ldsm4(qa[0][s][0],qa[0][s][1],qa[0][s][2],qa[0][s][3], qAddr + koff);
        ldsm4(qa[1][s][0],qa[1][s][1],qa[1][s][2],qa[1][s][3],
              qAddr + (uint32_t)(16*36*4) + koff);
    }

    float rowacc[4] = {0.f,0.f,0.f,0.f};

    for (int ti = 0; ti < TS; ti++){
        int b = ti & 1;
        if (ti + 1 < TS){
            stageK(1-b);
            if (ti + 2 < TS) ldgK((ti+2)*64);
        }
        uint32_t kA = kAddr + (uint32_t)b*KBUF;

        float acc[2][4][4];
        #pragma unroll
        for (int i=0;i<2;i++)
            #pragma unroll
            for (int j=0;j<4;j++)
                #pragma unroll
                for (int r=0;r<4;r++) acc[i][j][r]=0.f;

        #pragma unroll
        for (int s=0; s<4; s++){
            uint32_t koff = (uint32_t)(s*32);
            uint32_t b0[4], b1[4];
            ldsm4(b0[0],b0[1],b0[2],b0[3], kA + koff);
            ldsm4(b1[0],b1[1],b1[2],b1[3], kA + (uint32_t)(16*36*4) + koff);
            mma16(acc[0][0], qa[0][s][0],qa[0][s][1],qa[0][s][2],qa[0][s][3], b0[0],b0[1]);
            mma16(acc[0][1], qa[0][s][0],qa[0][s][1],qa[0][s][2],qa[0][s][3], b0[2],b0[3]);
            mma16(acc[0][2], qa[0][s][0],qa[0][s][1],qa[0][s][2],qa[0][s][3], b1[0],b1[1]);
            mma16(acc[0][3], qa[0][s][0],qa[0][s][1],qa[0][s][2],qa[0][s][3], b1[2],b1[3]);
            mma16(acc[1][0], qa[1][s][0],qa[1][s][1],qa[1][s][2],qa[1][s][3], b0[0],b0[1]);
            mma16(acc[1][1], qa[1][s][0],qa[1][s][1],qa[1][s][2],qa[1][s][3], b0[2],b0[3]);
            mma16(acc[1][2], qa[1][s][0],qa[1][s][1],qa[1][s][2],qa[1][s][3], b1[0],b1[1]);
            mma16(acc[1][3], qa[1][s][0],qa[1][s][1],qa[1][s][2],qa[1][s][3], b1[2],b1[3]);
        }
        #pragma unroll
        for (int mi=0;mi<2;mi++)
            #pragma unroll
            for (int ni=0;ni<4;ni++)
                #pragma unroll
                for (int r2=0;r2<4;r2++)
                    rowacc[mi*2 + (r2>>1)] += ex2f(acc[mi][ni][r2]);
        __syncthreads();
    }

    #pragma unroll
    for (int i=0;i<4;i++){
        float v = rowacc[i];
        v += __shfl_xor_sync(0xffffffffu, v, 1);
        v += __shfl_xor_sync(0xffffffffu, v, 2);
        if (tg == 0){
            int row = wm*32 + (i>>1)*16 + g + (i&1)*8;
            atomicAdd(&rs[row], v);
        }
    }
    __syncthreads();
    if (tid < 128)
        g_rsp[(size_t)z*BH*S_ + (size_t)bh*S_ + s0 + tid] = rs[tid];
}

// ---------------- pass 2: attn write + partial ctx = attn @ V, split over t ----------------
__global__ __launch_bounds__(256)
void attn_pv(float* __restrict__ attn)
{
    extern __shared__ uint32_t sm2[];
    uint32_t (*Qs)[36] = (uint32_t(*)[36])sm2;                          // 128
    uint32_t (*Ks)[36] = (uint32_t(*)[36])(sm2 + 128*36);               // 2 x 64
    uint32_t (*Vs)[36] = (uint32_t(*)[36])(sm2 + 256*36);               // 2 x 64
    float *rsv = (float*)(sm2 + 384*36);                                // 128
    float (*sctx)[66] = (float(*)[66])sm2;                              // alias (epilogue)

    const int TS = 32 / PV_SPLIT;
    int tid = threadIdx.x;
    int lane = tid & 31, wid = tid >> 5;
    int g = lane >> 2, tg = lane & 3;
    int wm = wid & 3, wn = wid >> 2;
    int bh = blockIdx.y;
    int s0 = blockIdx.x * 128;
    int z  = blockIdx.z;
    int tbase = z * (S_/PV_SPLIT);

    const __half* qh = g_Qh + ((size_t)bh*S_ + s0)*DEPTH;
    const __half* kh = g_Kh + ((size_t)bh*S_ + tbase)*DEPTH;
    const __half* vt = g_Vt +  (size_t)bh*DEPTH*S_ + tbase;
    float* attn_strip = attn + ((size_t)bh*S_ + s0)*S_ + tbase;
    float* ctxp = g_ctxp + (size_t)z*B_*S_*D_;

    uint32_t qAddr = s2u(&Qs[0][0]) + (uint32_t)(wm*32*36*4) + A_LANE_OFF(lane, 36);
    uint32_t kAddr = s2u(&Ks[0][0]) + (uint32_t)(wn*32*36*4) + B_LANE_OFF(lane, 36);
    uint32_t vAddr = s2u(&Vs[0][0]) + B_LANE_OFF(lane, 36);
    const uint32_t TBUF = 64*36*4;

    #pragma unroll
    for (int i=0;i<4;i++){
        int u = tid + i*256;
        int r = u>>3, c8 = u&7;
        *(uint4*)&Qs[r][c8*4] = *(const uint4*)(qh + (size_t)r*DEPTH + c8*8);
    }
    if (tid < 128){
        size_t idx = (size_t)bh*S_ + s0 + tid;
        float s = 0.f;
        #pragma unroll
        for (int zz=0; zz<RS_SPLIT; zz++) s += g_rsp[(size_t)zz*BH*S_ + idx];
        rsv[tid] = 1.0f / s;
    }

    uint4 kr[2], vr[2];
    auto ldgKV = [&](int t0){
        #pragma unroll
        for (int i=0;i<2;i++){
            int u = tid + i*256;
            int r = u>>3, c8 = u&7;
            kr[i] = *(const uint4*)(kh + (size_t)(t0+r)*DEPTH + c8*8);
            vr[i] = *(const uint4*)(vt + (size_t)r*S_ + t0 + c8*8);
        }
    };
    auto stageKV = [&](int buf){
        #pragma unroll
        for (int i=0;i<2;i++){
            int u = tid + i*256;
            int r = u>>3, c8 = u&7;
            *(uint4*)&Ks[buf*64 + r][c8*4] = kr[i];
            *(uint4*)&Vs[buf*64 + r][c8*4] = vr[i];
        }
    };

    ldgKV(0);
    stageKV(0);
    if (TS > 1) ldgKV(64);
    __syncthreads();

    float octx[2][8][4];
    #pragma unroll
    for (int i=0;i<2;i++)
        #pragma unroll
        for (int j=0;j<8;j++)
            #pragma unroll
            for (int r=0;r<4;r++) octx[i][j][r]=0.f;

    for (int ti = 0; ti < TS; ti++){
        int b = ti & 1;
        int t0 = ti*64;
        if (ti + 1 < TS){
            stageKV(1-b);
            if (ti + 2 < TS) ldgKV((ti+2)*64);
        }
        uint32_t kA = kAddr + (uint32_t)b*TBUF;
        uint32_t vA = vAddr + (uint32_t)b*TBUF;

        float acc[2][4][4];
        #pragma unroll
        for (int i=0;i<2;i++)
            #pragma unroll
            for (int j=0;j<4;j++)
                #pragma unroll
                for (int r=0;r<4;r++) acc[i][j][r]=0.f;

        #pragma unroll
        for (int s=0; s<4; s++){
            uint32_t koff = (uint32_t)(s*32);
            uint32_t a0[4], a1[4], b0[4], b1[4];
            ldsm4(a0[0],a0[1],a0[2],a0[3], qAddr + koff);
            ldsm4(a1[0],a1[1],a1[2],a1[3], qAddr + (uint32_t)(16*36*4) + koff);
            ldsm4(b0[0],b0[1],b0[2],b0[3], kA + koff);
            ldsm4(b1[0],b1[1],b1[2],b1[3], kA + (uint32_t)(16*36*4) + koff);
            mma16(acc[0][0], a0[0],a0[1],a0[2],a0[3], b0[0],b0[1]);
            mma16(acc[0][1], a0[0],a0[1],a0[2],a0[3], b0[2],b0[3]);
            mma16(acc[0][2], a0[0],a0[1],a0[2],a0[3], b1[0],b1[1]);
            mma16(acc[0][3], a0[0],a0[1],a0[2],a0[3], b1[2],b1[3]);
            mma16(acc[1][0], a1[0],a1[1],a1[2],a1[3], b0[0],b0[1]);
            mma16(acc[1][1], a1[0],a1[1],a1[2],a1[3], b0[2],b0[3]);
            mma16(acc[1][2], a1[0],a1[1],a1[2],a1[3], b1[0],b1[1]);
            mma16(acc[1][3], a1[0],a1[1],a1[2],a1[3], b1[2],b1[3]);
        }

        #pragma unroll
        for (int mi=0;mi<2;mi++){
            int r0 = wm*32 + mi*16 + g;
            float inv0 = rsv[r0], inv1 = rsv[r0+8];
            #pragma unroll
            for (int ni=0;ni<4;ni++){
                acc[mi][ni][0] = ex2f(acc[mi][ni][0])*inv0;
                acc[mi][ni][1] = ex2f(acc[mi][ni][1])*inv0;
                acc[mi][ni][2] = ex2f(acc[mi][ni][2])*inv1;
                acc[mi][ni][3] = ex2f(acc[mi][ni][3])*inv1;
            }
        }
        #pragma unroll
        for (int mi=0;mi<2;mi++)
            #pragma unroll
            for (int ni=0;ni<4;ni++)
                #pragma unroll
                for (int half=0; half<2; half++){
                    int rloc = wm*32 + mi*16 + g + half*8;
                    int cloc = wn*32 + ni*8 + tg*2;
                    *(float2*)(attn_strip + (size_t)rloc*S_ + t0 + cloc) =
                        make_float2(acc[mi][ni][half*2], acc[mi][ni][half*2+1]);
                }

        #pragma unroll
        for (int j=0; j<2; j++){
            uint32_t pa[2][4];
            #pragma unroll
            for (int mi=0;mi<2;mi++){
                pa[mi][0] = pack2(acc[mi][2*j  ][0], acc[mi][2*j  ][1]);
                pa[mi][1] = pack2(acc[mi][2*j  ][2], acc[mi][2*j  ][3]);
                pa[mi][2] = pack2(acc[mi][2*j+1][0], acc[mi][2*j+1][1]);
                pa[mi][3] = pack2(acc[mi][2*j+1][2], acc[mi][2*j+1][3]);
            }
            uint32_t koff = (uint32_t)((wn*16 + j*8)*4);
            #pragma unroll
            for (int rb=0; rb<4; rb++){
                uint32_t b2[4];
                ldsm4(b2[0],b2[1],b2[2],b2[3], vA + (uint32_t)(rb*16*36*4) + koff);
                mma16(octx[0][2*rb  ], pa[0][0],pa[0][1],pa[0][2],pa[0][3], b2[0],b2[1]);
                mma16(octx[0][2*rb+1], pa[0][0],pa[0][1],pa[0][2],pa[0][3], b2[2],b2[3]);
                mma16(octx[1][2*rb  ], pa[1][0],pa[1][1],pa[1][2],pa[1][3], b2[0],b2[1]);
                mma16(octx[1][2*rb+1], pa[1][0],pa[1][1],pa[1][2],pa[1][3], b2[2],b2[3]);
            }
        }
        __syncthreads();
    }

    // cross-warp (wn) reduction of partial ctx, then write partial buffer
    if (wn == 1){
        #pragma unroll
        for (int mi=0;mi<2;mi++)
            #pragma unroll
            for (int ni=0;ni<8;ni++)
                #pragma unroll
                for (int half=0; half<2; half++){
                    int rloc = wm*32 + mi*16 + g + half*8;
                    int col = ni*8 + tg*2;
                    sctx[rloc][col]   = octx[mi][ni][half*2];
                    sctx[rloc][col+1] = octx[mi][ni][half*2+1];
                }
    }
    __syncthreads();
    if (wn == 0){
        int b = bh >> 3, h = bh & 7;
        #pragma unroll
        for (int mi=0;mi<2;mi++)
            #pragma unroll
            for (int ni=0;ni<8;ni++)
                #pragma unroll
                for (int half=0; half<2; half++){
                    int rloc = wm*32 + mi*16 + g + half*8;
                    int col = ni*8 + tg*2;
                    float v0 = octx[mi][ni][half*2]   + sctx[rloc][col];
                    float v1 = octx[mi][ni][half*2+1] + sctx[rloc][col+1];
                    *(float2*)(ctxp + ((size_t)b*S_ + s0 + rloc)*D_ + h*64 + col) =
                        make_float2(v0, v1);
                }
    }
}

// ---------------- launch ----------------
extern "C" void kernel_launch(void* const* d_in, const int* in_sizes, int n_in,
                              void* d_out, int out_size)
{
    const float* q   = (const float*)d_in[0];
    const float* k   = (const float*)d_in[1];
    const float* v   = (const float*)d_in[2];
    const float* pe  = (const float*)d_in[3];
    // d_in[4] = mask (unused by reference)
    const float* Wq  = (const float*)d_in[5];
    const float* bq  = (const float*)d_in[6];
    const float* Wk  = (const float*)d_in[7];
    const float* bk  = (const float*)d_in[8];
    const float* Wv  = (const float*)d_in[9];
    const float* bv  = (const float*)d_in[10];
    const float* Wd  = (const float*)d_in[11];
    const float* bd  = (const float*)d_in[12];

    float* out  = (float*)d_out;                       // (B,S,D)
    float* attn = out + (size_t)B_*S_*D_;              // (B,H,S,S)

    float* Ctxp;
    cudaGetSymbolAddress((void**)&Ctxp, g_ctxp);

    transW<<<dim3(8, 8, 4), 256>>>(Wq, Wk, Wv, Wd);
    proj3<<<dim3(4, 64, 3), 256>>>(q, k, pe, v, bq, bk, bv, bd);
    transV<<<dim3(S_/64, BH), 256>>>();

    size_t smA = (size_t)(128*36 + 2*64*36)*sizeof(uint32_t) + 128*sizeof(float);
    cudaFuncSetAttribute(attn_rowsum, cudaFuncAttributeMaxDynamicSharedMemorySize, (int)smA);
    attn_rowsum<<<dim3(16, BH, RS_SPLIT), 256, smA>>>();

    size_t smB = (size_t)(128*36 + 4*64*36)*sizeof(uint32_t) + 128*sizeof(float);
    cudaFuncSetAttribute(attn_pv, cudaFuncAttributeMaxDynamicSharedMemorySize, (int)smB);
    attn_pv<<<dim3(16, BH, PV_SPLIT), 256, smB>>>(attn);

    gemm_out<<<dim3(4, 64), 256>>>(Ctxp, bd, out);
}

// round 17
// speedup vs baseline: 1.1715x; 1.0614x over previous
#include <cuda_runtime.h>
#include <cuda_fp16.h>
#include <cstdint>
#include <cstddef>

#define B_  4
#define S_  2048
#define D_  512
#define H_  8
#define DEPTH 64
#define BH  (B_*H_)

#define QSCALE 0.1803368801111832f   // log2(e)/8
#define RS_SPLIT 4
#define PV_SPLIT 2

// ---------------- scratch ----------------
__device__ __half g_WT[(size_t)4*512*512];      // W^T fp16 [which][n][k]
__device__ __half g_Qh[(size_t)BH*S_*DEPTH];    // Q'·log2e/8 fp16 head-split
__device__ __half g_Kh[(size_t)BH*S_*DEPTH];    // K'' fp16 head-split
__device__ __half g_Vt[(size_t)BH*DEPTH*S_];    // V'^T fp16 (bh,d,t) — written directly by proj
__device__ float  g_ctxp[(size_t)PV_SPLIT*B_*S_*D_];   // ctx partials
__device__ float  g_rsp[(size_t)RS_SPLIT*BH*S_];       // rowsum partials

// ---------------- helpers ----------------
__device__ __forceinline__ uint32_t pack2(float a, float b){
    __half2 h = __floats2half2_rn(a, b);
    return *(uint32_t*)&h;
}
__device__ __forceinline__ float ex2f(float x){
    float y; asm("ex2.approx.ftz.f32 %0, %1;" : "=f"(y) : "f"(x)); return y;
}
__device__ __forceinline__ uint32_t s2u(const void* p){
    uint32_t r; asm("{ .reg .u64 t; cvta.to.shared.u64 t, %1; cvt.u32.u64 %0, t; }"
                    : "=r"(r) : "l"(p)); return r;
}
__device__ __forceinline__ void stcs2(float* p, float a, float b){
    asm volatile("st.global.cs.v2.f32 [%0], {%1,%2};" :: "l"(p), "f"(a), "f"(b) : "memory");
}
__device__ __forceinline__ void mma16(float c[4], uint32_t a0,uint32_t a1,uint32_t a2,uint32_t a3,
                                      uint32_t b0,uint32_t b1){
    asm volatile("mma.sync.aligned.m16n8k16.row.col.f32.f16.f16.f32 "
        "{%0,%1,%2,%3}, {%4,%5,%6,%7}, {%8,%9}, {%0,%1,%2,%3};"
        : "+f"(c[0]),"+f"(c[1]),"+f"(c[2]),"+f"(c[3])
        : "r"(a0),"r"(a1),"r"(a2),"r"(a3),"r"(b0),"r"(b1));
}
__device__ __forceinline__ void ldsm4(uint32_t &r0,uint32_t &r1,uint32_t &r2,uint32_t &r3,
                                      uint32_t addr){
    asm volatile("ldmatrix.sync.aligned.m8n8.x4.shared.b16 {%0,%1,%2,%3}, [%4];"
        : "=r"(r0),"=r"(r1),"=r"(r2),"=r"(r3) : "r"(addr));
}

#define A_LANE_OFF(l, SW) (((((l)&7) + (((l)>>3)&1)*8) * (SW) + (((l)>>4)&1)*4) * 4)
#define B_LANE_OFF(l, SW) (((((l)&7) + (((l)>>4)&1)*8) * (SW) + (((l)>>3)&1)*4) * 4)

// ---------------- W transpose + fp16 convert ----------------
__global__ __launch_bounds__(256)
void transW(const float* Wq, const float* Wk, const float* Wv, const float* Wd)
{
    __shared__ float ts[64][65];
    const float* W = (blockIdx.z==0)?Wq:(blockIdx.z==1)?Wk:(blockIdx.z==2)?Wv:Wd;
    __half* WT = g_WT + (size_t)blockIdx.z*512*512;
    int k0 = blockIdx.y*64, n0 = blockIdx.x*64;
    int tid = threadIdx.x;
    #pragma unroll
    for (int i=0;i<4;i++){
        int e = tid + i*256;
        int r = e>>4, c = (e&15)*4;
        float4 x = *(const float4*)(W + (size_t)(k0+r)*512 + n0 + c);
        ts[r][c]=x.x; ts[r][c+1]=x.y; ts[r][c+2]=x.z; ts[r][c+3]=x.w;
    }
    __syncthreads();
    #pragma unroll
    for (int i=0;i<2;i++){
        int u = tid + i*256;
        int n = u>>3, seg = (u&7)*8;
        uint32_t h[4];
        #pragma unroll
        for (int j=0;j<4;j++)
            h[j] = pack2(ts[seg+2*j][n], ts[seg+2*j+1][n]);
        *(uint4*)(WT + (size_t)(n0+n)*512 + k0 + seg) = make_uint4(h[0],h[1],h[2],h[3]);
    }
}

// ---------------- fp16 GEMM core, 128x128 tiles (double-buffered smem) ----------------
// OUTMODE: 0 = fp32 row-major Cf, 1 = fp16 head-split Ch, 2 = fp16 V^T (bh,d,t)
// ADDA: sum PV_SPLIT ctx partial buffers (fixed order, deterministic).
template<int OUTMODE, int ADDA>
__device__ __forceinline__ void gemm16_core(
    const float* __restrict__ A1,
    const __half* __restrict__ BT1, const float* __restrict__ bias1,
    const float* __restrict__ A2, const __half* __restrict__ BT2, const float* __restrict__ bias2,
    float* __restrict__ Cf, __half* __restrict__ Ch, int m0, int n0, float oscale,
    uint32_t (*As)[20], uint32_t (*Bs)[20])
{
    int tid = threadIdx.x;
    int lane = tid & 31, wid = tid >> 5;
    int g = lane >> 2, tg = lane & 3;
    int wm = wid & 3, wn = wid >> 2;

    float acc[2][8][4];
    #pragma unroll
    for (int i=0;i<2;i++)
        #pragma unroll
        for (int j=0;j<8;j++)
            #pragma unroll
            for (int r=0;r<4;r++) acc[i][j][r]=0.f;

    uint32_t aAddr = s2u(&As[0][0]) + (uint32_t)(wm*32*20*4) + A_LANE_OFF(lane, 20);
    uint32_t bAddr = s2u(&Bs[0][0]) + (uint32_t)(wn*64*20*4) + B_LANE_OFF(lane, 20);
    const uint32_t ABUF = 128*20*4, BBUF = 128*20*4;

    const int ntile = A2 ? 32 : 16;
    float4 ra[4]; uint4 rb2[2];
    auto ldg_tile = [&](int t){
        const float* A   = (t >= 16) ? A2  : A1;
        const __half* BT = (t >= 16) ? BT2 : BT1;
        int k0 = (t & 15) * 32;
        #pragma unroll
        for (int i=0;i<4;i++){
            int e = tid + i*256; int r = e>>3, c = (e&7)*4;
            ra[i] = *(const float4*)(A + (size_t)(m0+r)*512 + k0 + c);
            if (ADDA){
                #pragma unroll
                for (int zz=1; zz<PV_SPLIT; zz++){
                    float4 x = *(const float4*)(A + (size_t)zz*B_*S_*D_ + (size_t)(m0+r)*512 + k0 + c);
                    ra[i].x += x.x; ra[i].y += x.y; ra[i].z += x.z; ra[i].w += x.w;
                }
            }
        }
        int n = tid>>1, kc = (tid&1)*16;
        rb2[0] = *(const uint4*)(BT + (size_t)(n0+n)*512 + k0 + kc);
        rb2[1] = *(const uint4*)(BT + (size_t)(n0+n)*512 + k0 + kc + 8);
    };
    auto stage = [&](int buf){
        #pragma unroll
        for (int i=0;i<4;i++){
            int e = tid + i*256; int r = e>>3, c = (e&7)*4;
            *(uint2*)&As[buf*128 + r][c>>1] =
                make_uint2(pack2(ra[i].x, ra[i].y), pack2(ra[i].z, ra[i].w));
        }
        int n = tid>>1, seg = (tid&1)*8;
        *(uint4*)&Bs[buf*128 + n][seg]     = rb2[0];
        *(uint4*)&Bs[buf*128 + n][seg + 4] = rb2[1];
    };

    ldg_tile(0);
    stage(0);
    if (ntile > 1) ldg_tile(1);
    __syncthreads();

    for (int t = 0; t < ntile; t++){
        int b = t & 1;
        if (t+1 < ntile){
            stage(1-b);
            if (t+2 < ntile) ldg_tile(t+2);
        }
        uint32_t aA = aAddr + (uint32_t)b*ABUF;
        uint32_t bA = bAddr + (uint32_t)b*BBUF;
        #pragma unroll
        for (int s=0; s<2; s++){
            uint32_t koff = (uint32_t)(s*32);
            uint32_t a0[4], a1[4], bb[4][4];
            ldsm4(a0[0],a0[1],a0[2],a0[3], aA + koff);
            ldsm4(a1[0],a1[1],a1[2],a1[3], aA + (uint32_t)(16*20*4) + koff);
            #pragma unroll
            for (int rb=0; rb<4; rb++)
                ldsm4(bb[rb][0],bb[rb][1],bb[rb][2],bb[rb][3],
                      bA + (uint32_t)(rb*16*20*4) + koff);
            #pragma unroll
            for (int rb=0; rb<4; rb++){
                mma16(acc[0][2*rb  ], a0[0],a0[1],a0[2],a0[3], bb[rb][0],bb[rb][1]);
                mma16(acc[0][2*rb+1], a0[0],a0[1],a0[2],a0[3], bb[rb][2],bb[rb][3]);
                mma16(acc[1][2*rb  ], a1[0],a1[1],a1[2],a1[3], bb[rb][0],bb[rb][1]);
                mma16(acc[1][2*rb+1], a1[0],a1[1],a1[2],a1[3], bb[rb][2],bb[rb][3]);
            }
        }
        __syncthreads();
    }

    #pragma unroll
    for (int mi=0;mi<2;mi++)
        #pragma unroll
        for (int ni=0;ni<8;ni++)
            #pragma unroll
            for (int half=0; half<2; half++){
                int row = m0 + wm*32 + mi*16 + g + half*8;
                int col = n0 + wn*64 + ni*8 + tg*2;
                float b0v = bias1[col]   + (bias2 ? bias2[col]   : 0.f);
                float b1v = bias1[col+1] + (bias2 ? bias2[col+1] : 0.f);
                float v0 = (acc[mi][ni][half*2+0] + b0v) * oscale;
                float v1 = (acc[mi][ni][half*2+1] + b1v) * oscale;
                if (OUTMODE == 1){
                    int b = row >> 11, s = row & 2047;
                    int h = col >> 6,  d = col & 63;
                    size_t idx = (((size_t)(b*H_ + h))*S_ + s)*DEPTH + d;
                    *(uint32_t*)(Ch + idx) = pack2(v0, v1);
                } else if (OUTMODE == 2){
                    int b = row >> 11, s = row & 2047;
                    int h = col >> 6,  d = col & 63;
                    size_t base = ((size_t)(b*H_ + h)*DEPTH + d)*S_ + s;
                    Ch[base]      = __float2half(v0);
                    Ch[base + S_] = __float2half(v1);
                } else {
                    *(float2*)(Cf + (size_t)row*512 + col) = make_float2(v0, v1);
                }
            }
}

__global__ __launch_bounds__(256, 2)
void proj3(const float* q, const float* k, const float* pe, const float* v,
           const float* bq, const float* bk, const float* bv, const float* bd)
{
    __shared__ uint32_t As[2*128][20];
    __shared__ uint32_t Bs[2*128][20];
    int m0 = blockIdx.y*128, n0 = blockIdx.x*128;
    const __half* WqT = g_WT;
    const __half* WkT = g_WT + (size_t)512*512;
    const __half* WvT = g_WT + (size_t)2*512*512;
    const __half* WdT = g_WT + (size_t)3*512*512;
    if (blockIdx.z == 0)
        gemm16_core<1,0>(q, WqT, bq, nullptr,nullptr,nullptr, nullptr, g_Qh, m0,n0, QSCALE, As,Bs);
    else if (blockIdx.z == 1)
        gemm16_core<1,0>(k, WkT, bk, pe, WdT, bd, nullptr, g_Kh, m0,n0, 1.f, As,Bs);
    else
        gemm16_core<2,0>(v, WvT, bv, nullptr,nullptr,nullptr, nullptr, g_Vt, m0,n0, 1.f, As,Bs);
}

__global__ __launch_bounds__(256, 2)
void gemm_out(const float* __restrict__ A,
              const float* __restrict__ bd, float* __restrict__ C)
{
    __shared__ uint32_t As[2*128][20];
    __shared__ uint32_t Bs[2*128][20];
    gemm16_core<0,1>(A, g_WT + (size_t)3*512*512, bd, nullptr,nullptr,nullptr, C, nullptr,
                     blockIdx.y*128, blockIdx.x*128, 1.f, As, Bs);
}

// ---------------- pass 1: partial rowsums of exp(logits), split over t ----------------
__global__ __launch_bounds__(256)
void attn_rowsum()
{
    extern __shared__ uint32_t sm1[];
    uint32_t (*Qs)[36] = (uint32_t(*)[36])sm1;                    // 128
    uint32_t (*Ks)[36] = (uint32_t(*)[36])(sm1 + 128*36);         // 2 x 64
    float *rs = (float*)(sm1 + 128*36 + 2*64*36);

    const int TS = 32 / RS_SPLIT;    // tiles per split
    int tid = threadIdx.x;
    int lane = tid & 31, wid = tid >> 5;
    int g = lane >> 2, tg = lane & 3;
    int wm = wid & 3, wn = wid >> 2;
    int bh = blockIdx.y;
    int s0 = blockIdx.x * 128;
    int z  = blockIdx.z;

    const __half* qh = g_Qh + ((size_t)bh*S_ + s0)*DEPTH;
    const __half* kh = g_Kh + ((size_t)bh*S_ + z*(S_/RS_SPLIT))*DEPTH;

    uint32_t qAddr = s2u(&Qs[0][0]) + (uint32_t)(wm*32*36*4) + A_LANE_OFF(lane, 36);
    uint32_t kAddr = s2u(&Ks[0][0]) + (uint32_t)(wn*32*36*4) + B_LANE_OFF(lane, 36);
    const uint32_t KBUF = 64*36*4;

    #pragma unroll
    for (int i=0;i<4;i++){
        int u = tid + i*256;
        int r = u>>3, c8 = u&7;
        *(uint4*)&Qs[r][c8*4] = *(const uint4*)(qh + (size_t)r*DEPTH + c8*8);
    }
    if (tid < 128) rs[tid] = 0.f;

    uint4 kr[2];
    auto ldgK = [&](int t0){
        #pragma unroll
        for (int i=0;i<2;i++){
            int u = tid + i*256;
            int r = u>>3, c8 = u&7;
            kr[i] = *(const uint4*)(kh + (size_t)(t0+r)*DEPTH + c8*8);
        }
    };
    auto stageK = [&](int buf){
        #pragma unroll
        for (int i=0;i<2;i++){
            int u = tid + i*256;
            int r = u>>3, c8 = u&7;
            *(uint4*)&Ks[buf*64 + r][c8*4] = kr[i];
        }
    };

    ldgK(0);
    stageK(0);
    if (TS > 1) ldgK(64);
    __syncthreads();

    float rowacc[4] = {0.f,0.f,0.f,0.f};

    for (int ti = 0; ti < TS; ti++){
        int b = ti & 1;
        if (ti + 1 < TS){
            stageK(1-b);
            if (ti + 2 < TS) ldgK((ti+2)*64);
        }
        uint32_t kA = kAddr + (uint32_t)b*KBUF;

        float acc[2][4][4];
        #pragma unroll
        for (int i=0;i<2;i++)
            #pragma unroll
            for (int j=0;j<4;j++)
                #pragma unroll
                for (int r=0;r<4;r++) acc[i][j][r]=0.f;

        #pragma unroll
        for (int s=0; s<4; s++){
            uint32_t koff = (uint32_t)(s*32);
            uint32_t a0[4], a1[4], b0[4], b1[4];
            ldsm4(a0[0],a0[1],a0[2],a0[3], qAddr + koff);
            ldsm4(a1[0],a1[1],a1[2],a1[3], qAddr + (uint32_t)(16*36*4) + koff);
            ldsm4(b0[0],b0[1],b0[2],b0[3], kA + koff);
            ldsm4(b1[0],b1[1],b1[2],b1[3], kA + (uint32_t)(16*36*4) + koff);
            mma16(acc[0][0], a0[0],a0[1],a0[2],a0[3], b0[0],b0[1]);
            mma16(acc[0][1], a0[0],a0[1],a0[2],a0[3], b0[2],b0[3]);
            mma16(acc[0][2], a0[0],a0[1],a0[2],a0[3], b1[0],b1[1]);
            mma16(acc[0][3], a0[0],a0[1],a0[2],a0[3], b1[2],b1[3]);
            mma16(acc[1][0], a1[0],a1[1],a1[2],a1[3], b0[0],b0[1]);
            mma16(acc[1][1], a1[0],a1[1],a1[2],a1[3], b0[2],b0[3]);
            mma16(acc[1][2], a1[0],a1[1],a1[2],a1[3], b1[0],b1[1]);
            mma16(acc[1][3], a1[0],a1[1],a1[2],a1[3], b1[2],b1[3]);
        }
        #pragma unroll
        for (int mi=0;mi<2;mi++)
            #pragma unroll
            for (int ni=0;ni<4;ni++)
                #pragma unroll
                for (int r2=0;r2<4;r2++)
                    rowacc[mi*2 + (r2>>1)] += ex2f(acc[mi][ni][r2]);
        __syncthreads();
    }

    #pragma unroll
    for (int i=0;i<4;i++){
        float v = rowacc[i];
        v += __shfl_xor_sync(0xffffffffu, v, 1);
        v += __shfl_xor_sync(0xffffffffu, v, 2);
        if (tg == 0){
            int row = wm*32 + (i>>1)*16 + g + (i&1)*8;
            atomicAdd(&rs[row], v);
        }
    }
    __syncthreads();
    if (tid < 128)
        g_rsp[(size_t)z*BH*S_ + (size_t)bh*S_ + s0 + tid] = rs[tid];
}

// ---------------- pass 2: attn write + partial ctx = attn @ V, split over t ----------------
__global__ __launch_bounds__(256)
void attn_pv(float* __restrict__ attn)
{
    extern __shared__ uint32_t sm2[];
    uint32_t (*Qs)[36] = (uint32_t(*)[36])sm2;                          // 128
    uint32_t (*Ks)[36] = (uint32_t(*)[36])(sm2 + 128*36);               // 2 x 64
    uint32_t (*Vs)[36] = (uint32_t(*)[36])(sm2 + 256*36);               // 2 x 64
    float *rsv = (float*)(sm2 + 384*36);                                // 128
    float (*sctx)[66] = (float(*)[66])sm2;                              // alias (epilogue)

    const int TS = 32 / PV_SPLIT;
    int tid = threadIdx.x;
    int lane = tid & 31, wid = tid >> 5;
    int g = lane >> 2, tg = lane & 3;
    int wm = wid & 3, wn = wid >> 2;
    int bh = blockIdx.y;
    int s0 = blockIdx.x * 128;
    int z  = blockIdx.z;
    int tbase = z * (S_/PV_SPLIT);

    const __half* qh = g_Qh + ((size_t)bh*S_ + s0)*DEPTH;
    const __half* kh = g_Kh + ((size_t)bh*S_ + tbase)*DEPTH;
    const __half* vt = g_Vt +  (size_t)bh*DEPTH*S_ + tbase;
    float* attn_strip = attn + ((size_t)bh*S_ + s0)*S_ + tbase;
    float* ctxp = g_ctxp + (size_t)z*B_*S_*D_;

    uint32_t qAddr = s2u(&Qs[0][0]) + (uint32_t)(wm*32*36*4) + A_LANE_OFF(lane, 36);
    uint32_t kAddr = s2u(&Ks[0][0]) + (uint32_t)(wn*32*36*4) + B_LANE_OFF(lane, 36);
    uint32_t vAddr = s2u(&Vs[0][0]) + B_LANE_OFF(lane, 36);
    const uint32_t TBUF = 64*36*4;

    #pragma unroll
    for (int i=0;i<4;i++){
        int u = tid + i*256;
        int r = u>>3, c8 = u&7;
        *(uint4*)&Qs[r][c8*4] = *(const uint4*)(qh + (size_t)r*DEPTH + c8*8);
    }
    if (tid < 128){
        size_t idx = (size_t)bh*S_ + s0 + tid;
        float s = 0.f;
        #pragma unroll
        for (int zz=0; zz<RS_SPLIT; zz++) s += g_rsp[(size_t)zz*BH*S_ + idx];
        rsv[tid] = 1.0f / s;
    }

    uint4 kr[2], vr[2];
    auto ldgKV = [&](int t0){
        #pragma unroll
        for (int i=0;i<2;i++){
            int u = tid + i*256;
            int r = u>>3, c8 = u&7;
            kr[i] = *(const uint4*)(kh + (size_t)(t0+r)*DEPTH + c8*8);
            vr[i] = *(const uint4*)(vt + (size_t)r*S_ + t0 + c8*8);
        }
    };
    auto stageKV = [&](int buf){
        #pragma unroll
        for (int i=0;i<2;i++){
            int u = tid + i*256;
            int r = u>>3, c8 = u&7;
            *(uint4*)&Ks[buf*64 + r][c8*4] = kr[i];
            *(uint4*)&Vs[buf*64 + r][c8*4] = vr[i];
        }
    };

    ldgKV(0);
    stageKV(0);
    if (TS > 1) ldgKV(64);
    __syncthreads();

    float octx[2][8][4];
    #pragma unroll
    for (int i=0;i<2;i++)
        #pragma unroll
        for (int j=0;j<8;j++)
            #pragma unroll
            for (int r=0;r<4;r++) octx[i][j][r]=0.f;

    for (int ti = 0; ti < TS; ti++){
        int b = ti & 1;
        int t0 = ti*64;
        if (ti + 1 < TS){
            stageKV(1-b);
            if (ti + 2 < TS) ldgKV((ti+2)*64);
        }
        uint32_t kA = kAddr + (uint32_t)b*TBUF;
        uint32_t vA = vAddr + (uint32_t)b*TBUF;

        float acc[2][4][4];
        #pragma unroll
        for (int i=0;i<2;i++)
            #pragma unroll
            for (int j=0;j<4;j++)
                #pragma unroll
                for (int r=0;r<4;r++) acc[i][j][r]=0.f;

        #pragma unroll
        for (int s=0; s<4; s++){
            uint32_t koff = (uint32_t)(s*32);
            uint32_t a0[4], a1[4], b0[4], b1[4];
            ldsm4(a0[0],a0[1],a0[2],a0[3], qAddr + koff);
            ldsm4(a1[0],a1[1],a1[2],a1[3], qAddr + (uint32_t)(16*36*4) + koff);
            ldsm4(b0[0],b0[1],b0[2],b0[3], kA + koff);
            ldsm4(b1[0],b1[1],b1[2],b1[3], kA + (uint32_t)(16*36*4) + koff);
            mma16(acc[0][0], a0[0],a0[1],a0[2],a0[3], b0[0],b0[1]);
            mma16(acc[0][1], a0[0],a0[1],a0[2],a0[3], b0[2],b0[3]);
            mma16(acc[0][2], a0[0],a0[1],a0[2],a0[3], b1[0],b1[1]);
            mma16(acc[0][3], a0[0],a0[1],a0[2],a0[3], b1[2],b1[3]);
            mma16(acc[1][0], a1[0],a1[1],a1[2],a1[3], b0[0],b0[1]);
            mma16(acc[1][1], a1[0],a1[1],a1[2],a1[3], b0[2],b0[3]);
            mma16(acc[1][2], a1[0],a1[1],a1[2],a1[3], b1[0],b1[1]);
            mma16(acc[1][3], a1[0],a1[1],a1[2],a1[3], b1[2],b1[3]);
        }

        #pragma unroll
        for (int mi=0;mi<2;mi++){
            int r0 = wm*32 + mi*16 + g;
            float inv0 = rsv[r0], inv1 = rsv[r0+8];
            #pragma unroll
            for (int ni=0;ni<4;ni++){
                acc[mi][ni][0] = ex2f(acc[mi][ni][0])*inv0;
                acc[mi][ni][1] = ex2f(acc[mi][ni][1])*inv0;
                acc[mi][ni][2] = ex2f(acc[mi][ni][2])*inv1;
                acc[mi][ni][3] = ex2f(acc[mi][ni][3])*inv1;
            }
        }
        #pragma unroll
        for (int mi=0;mi<2;mi++)
            #pragma unroll
            for (int ni=0;ni<4;ni++)
                #pragma unroll
                for (int half=0; half<2; half++){
                    int rloc = wm*32 + mi*16 + g + half*8;
                    int cloc = wn*32 + ni*8 + tg*2;
                    stcs2(attn_strip + (size_t)rloc*S_ + t0 + cloc,
                          acc[mi][ni][half*2], acc[mi][ni][half*2+1]);
                }

        #pragma unroll
        for (int j=0; j<2; j++){
            uint32_t pa[2][4];
            #pragma unroll
            for (int mi=0;mi<2;mi++){
                pa[mi][0] = pack2(acc[mi][2*j  ][0], acc[mi][2*j  ][1]);
                pa[mi][1] = pack2(acc[mi][2*j  ][2], acc[mi][2*j  ][3]);
                pa[mi][2] = pack2(acc[mi][2*j+1][0], acc[mi][2*j+1][1]);
                pa[mi][3] = pack2(acc[mi][2*j+1][2], acc[mi][2*j+1][3]);
            }
            uint32_t koff = (uint32_t)((wn*16 + j*8)*4);
            #pragma unroll
            for (int rb=0; rb<4; rb++){
                uint32_t b2[4];
                ldsm4(b2[0],b2[1],b2[2],b2[3], vA + (uint32_t)(rb*16*36*4) + koff);
                mma16(octx[0][2*rb  ], pa[0][0],pa[0][1],pa[0][2],pa[0][3], b2[0],b2[1]);
                mma16(octx[0][2*rb+1], pa[0][0],pa[0][1],pa[0][2],pa[0][3], b2[2],b2[3]);
                mma16(octx[1][2*rb  ], pa[1][0],pa[1][1],pa[1][2],pa[1][3], b2[0],b2[1]);
                mma16(octx[1][2*rb+1], pa[1][0],pa[1][1],pa[1][2],pa[1][3], b2[2],b2[3]);
            }
        }
        __syncthreads();
    }

    // cross-warp (wn) reduction of partial ctx, then write partial buffer
    if (wn == 1){
        #pragma unroll
        for (int mi=0;mi<2;mi++)
            #pragma unroll
            for (int ni=0;ni<8;ni++)
                #pragma unroll
                for (int half=0; half<2; half++){
                    int rloc = wm*32 + mi*16 + g + half*8;
                    int col = ni*8 + tg*2;
                    sctx[rloc][col]   = octx[mi][ni][half*2];
                    sctx[rloc][col+1] = octx[mi][ni][half*2+1];
                }
    }
    __syncthreads();
    if (wn == 0){
        int b = bh >> 3, h = bh & 7;
        #pragma unroll
        for (int mi=0;mi<2;mi++)
            #pragma unroll
            for (int ni=0;ni<8;ni++)
                #pragma unroll
                for (int half=0; half<2; half++){
                    int rloc = wm*32 + mi*16 + g + half*8;
                    int col = ni*8 + tg*2;
                    float v0 = octx[mi][ni][half*2]   + sctx[rloc][col];
                    float v1 = octx[mi][ni][half*2+1] + sctx[rloc][col+1];
                    *(float2*)(ctxp + ((size_t)b*S_ + s0 + rloc)*D_ + h*64 + col) =
                        make_float2(v0, v1);
                }
    }
}

// ---------------- launch ----------------
extern "C" void kernel_launch(void* const* d_in, const int* in_sizes, int n_in,
                              void* d_out, int out_size)
{
    const float* q   = (const float*)d_in[0];
    const float* k   = (const float*)d_in[1];
    const float* v   = (const float*)d_in[2];
    const float* pe  = (const float*)d_in[3];
    // d_in[4] = mask (unused by reference)
    const float* Wq  = (const float*)d_in[5];
    const float* bq  = (const float*)d_in[6];
    const float* Wk  = (const float*)d_in[7];
    const float* bk  = (const float*)d_in[8];
    const float* Wv  = (const float*)d_in[9];
    const float* bv  = (const float*)d_in[10];
    const float* Wd  = (const float*)d_in[11];
    const float* bd  = (const float*)d_in[12];

    float* out  = (float*)d_out;                       // (B,S,D)
    float* attn = out + (size_t)B_*S_*D_;              // (B,H,S,S)

    float* Ctxp;
    cudaGetSymbolAddress((void**)&Ctxp, g_ctxp);

    transW<<<dim3(8, 8, 4), 256>>>(Wq, Wk, Wv, Wd);
    proj3<<<dim3(4, 64, 3), 256>>>(q, k, pe, v, bq, bk, bv, bd);

    size_t smA = (size_t)(128*36 + 2*64*36)*sizeof(uint32_t) + 128*sizeof(float);
    cudaFuncSetAttribute(attn_rowsum, cudaFuncAttributeMaxDynamicSharedMemorySize, (int)smA);
    attn_rowsum<<<dim3(16, BH, RS_SPLIT), 256, smA>>>();

    size_t smB = (size_t)(128*36 + 4*64*36)*sizeof(uint32_t) + 128*sizeof(float);
    cudaFuncSetAttribute(attn_pv, cudaFuncAttributeMaxDynamicSharedMemorySize, (int)smB);
    attn_pv<<<dim3(16, BH, PV_SPLIT), 256, smB>>>(attn);

    gemm_out<<<dim3(4, 64), 256>>>(Ctxp, bd, out);
}